// round 8
// baseline (speedup 1.0000x reference)
#include <cuda_runtime.h>
#include <cuda_bf16.h>

// ENAHPool collapses analytically:
//   sums = ssum/(ssum+1e-16) ~= 1.0 per channel (or 0 for isolated nodes):
//   assign rows are constant vectors, so S = softmax(assign,-1) = 1/256
//   everywhere.
//   => x_pooled[p,c]   = colsum(x)[c] / 256            (broadcast over p)
//   => adj_pooled[p,q] = nnz_unique(edges) / 65536     (scalar broadcast)
// nnz must dedup (row,col) pairs: .at[].set(1.0); ~512 expected dups at
// E=262144 random pairs in 8192^2 (2e-3 relative if skipped -> mandatory).

#define NN 8192
#define EE 262144
#define CC 256
#define BM_WORDS 2097152   // 8192*8192 / 32 = 8 MB bitmap
#define NPART 64

__device__ unsigned int       g_bitmap[BM_WORDS];
__device__ unsigned long long g_nnz;
__device__ int                g_is64;
__device__ float              g_partial[NPART][CC];
__device__ float              g_colsum[CC];

// ---- dtype detection: int64 indices (vals 0..8191) have all-zero odd words -
__global__ void k_detect(const unsigned int* __restrict__ w) {
    __shared__ unsigned int acc[256];
    int t = threadIdx.x;
    acc[t] = w[2 * t + 1];
    __syncthreads();
    for (int s = 128; s; s >>= 1) {
        if (t < s) acc[t] |= acc[t + s];
        __syncthreads();
    }
    if (t == 0) g_is64 = (acc[0] == 0u) ? 1 : 0;
}

// ---- zero the bitmap (uint4 stores) + nnz counter --------------------------
__global__ void k_zero(void) {
    unsigned int i = blockIdx.x * blockDim.x + threadIdx.x;
    uint4* bm4 = reinterpret_cast<uint4*>(g_bitmap);
    const unsigned int n4 = BM_WORDS / 4;
    if (i < n4) bm4[i] = make_uint4(0u, 0u, 0u, 0u);
    if (i == 0) g_nnz = 0ULL;
}

// ---- deterministic column-sum of x [NN, CC]: pass 1 (64 fixed partials) ----
__global__ void k_colsum_partial(const float* __restrict__ x) {
    const int b = blockIdx.x;           // 0..63
    const int t = threadIdx.x;          // 0..255 = column
    const int rows_per = NN / NPART;    // 128
    const float* p = x + (long long)(b * rows_per) * CC + t;
    float s = 0.0f;
    #pragma unroll 8
    for (int r = 0; r < rows_per; ++r) s += p[(long long)r * CC];
    g_partial[b][t] = s;
}

// ---- pass 2: fixed-order reduce of the 64 partials -------------------------
__global__ void k_colsum_final(void) {
    const int t = threadIdx.x;          // 256 threads, 1 block
    float s = 0.0f;
    #pragma unroll
    for (int b = 0; b < NPART; ++b) s += g_partial[b][t];
    g_colsum[t] = s;
}

// ---- set one bit per edge (dedup happens in the bitmap) --------------------
__global__ void k_edges(const unsigned int* __restrict__ w) {
    int e = blockIdx.x * blockDim.x + threadIdx.x;
    if (e >= EE) return;
    unsigned int r, c;
    if (g_is64) {                        // int64 little-endian: low words only
        r = w[2 * e];
        c = w[2 * (EE + e)];
    } else {                             // int32
        r = w[e];
        c = w[EE + e];
    }
    if (r >= NN || c >= NN) return;      // defensive: report, don't crash
    unsigned int idx_hi = r << 8 | (c >> 5);     // (r*8192 + c) / 32
    atomicOr(&g_bitmap[idx_hi], 1u << (c & 31));
}

// ---- popcount-reduce the bitmap -> g_nnz (integer atomics, deterministic) --
__global__ void k_popcount(void) {
    unsigned int cnt = 0;
    const uint4* bm4 = reinterpret_cast<const uint4*>(g_bitmap);
    const unsigned int n4 = BM_WORDS / 4;
    const unsigned int stride = gridDim.x * blockDim.x;
    for (unsigned int j = blockIdx.x * blockDim.x + threadIdx.x; j < n4; j += stride) {
        uint4 v = bm4[j];
        cnt += __popc(v.x) + __popc(v.y) + __popc(v.z) + __popc(v.w);
    }
    #pragma unroll
    for (int o = 16; o; o >>= 1) cnt += __shfl_down_sync(0xffffffffu, cnt, o);
    __shared__ unsigned int ws[32];
    int lane = threadIdx.x & 31, wp = threadIdx.x >> 5;
    if (lane == 0) ws[wp] = cnt;
    __syncthreads();
    if (wp == 0) {
        unsigned int nwarps = blockDim.x >> 5;
        unsigned int v = (lane < (int)nwarps) ? ws[lane] : 0u;
        #pragma unroll
        for (int o = 16; o; o >>= 1) v += __shfl_down_sync(0xffffffffu, v, o);
        if (lane == 0) atomicAdd(&g_nnz, (unsigned long long)v);
    }
}

// ---- emit output: [x_pooled (256x256), adj_pooled (256x256)] ---------------
__global__ void k_output(float* __restrict__ out, int out_size) {
    int i = blockIdx.x * blockDim.x + threadIdx.x;
    if (i >= out_size) return;
    const int XPOOL_ELEMS = 256 * CC;   // 65536
    if (i < XPOOL_ELEMS) {
        out[i] = g_colsum[i & (CC - 1)] * (1.0f / 256.0f);
    } else {
        out[i] = (float)g_nnz * (1.0f / 65536.0f);
    }
}

extern "C" void kernel_launch(void* const* d_in, const int* in_sizes, int n_in,
                              void* d_out, int out_size) {
    const float*        x  = (const float*)d_in[0];
    const unsigned int* ei = (const unsigned int*)d_in[1];
    float* out = (float*)d_out;

    k_detect<<<1, 256>>>(ei);
    k_zero<<<(BM_WORDS / 4 + 255) / 256, 256>>>();
    k_colsum_partial<<<NPART, 256>>>(x);
    k_colsum_final<<<1, 256>>>();
    k_edges<<<(EE + 255) / 256, 256>>>(ei);
    k_popcount<<<256, 256>>>();
    k_output<<<(out_size + 255) / 256, 256>>>(out, out_size);
}

// round 12
// speedup vs baseline: 1.1116x; 1.1116x over previous
#include <cuda_runtime.h>
#include <cuda_bf16.h>

// ENAHPool collapses analytically (verified R8: rel_err 4.2e-7):
//   S = softmax(assign,-1) = 1/256 everywhere (assign rows are constant).
//   => x_pooled[p,c]   = colsum(x)[c] / 256          (broadcast over p)
//   => adj_pooled[p,q] = nnz_unique(edges) / 65536   (scalar broadcast)
//
// R8 -> R9 optimization:
//  * nnz counted INLINE in the edge kernel via atomicOr old-value + warp
//    ballot (exactly one thread sees the bit unset -> deterministic count).
//    Kills the 8MB popcount pass.
//  * single-block k_colsum_final (6.2us straggler) replaced by per-block
//    recompute from L2-resident partials inside the output kernel.
//  * bitmap zeroing moved to the END (kernel C): globals start zero, each
//    call leaves the bitmap clean -> invariant across graph replays.
//  7 launches -> 3.

#define NN 8192
#define EE 262144
#define CC 256
#define BM_WORDS 2097152   // 8192*8192 / 32 = 8 MB bitmap
#define NPART 128

__device__ unsigned int       g_bitmap[BM_WORDS];   // zero-init, self-cleaning
__device__ unsigned long long g_nnz;
__device__ int                g_is64;
__device__ float              g_partial[NPART][CC];

// ---- A: colsum partials (blocks 0..127) + dtype detect / nnz reset (128) ---
__global__ void k_A(const float* __restrict__ x, const unsigned int* __restrict__ w) {
    __shared__ unsigned int acc[256];
    const int b = blockIdx.x;
    const int t = threadIdx.x;
    if (b < NPART) {
        const int rows_per = NN / NPART;             // 64
        const float* p = x + (long long)(b * rows_per) * CC + t;
        float s = 0.0f;
        #pragma unroll 8
        for (int r = 0; r < rows_per; ++r) s += p[(long long)r * CC];
        g_partial[b][t] = s;
    } else {
        // int64 little-endian indices (vals < 8192) => odd 32-bit words all 0
        acc[t] = w[2 * t + 1];
        __syncthreads();
        for (int s = 128; s; s >>= 1) {
            if (t < s) acc[t] |= acc[t + s];
            __syncthreads();
        }
        if (t == 0) {
            g_is64 = (acc[0] == 0u) ? 1 : 0;
            g_nnz  = 0ULL;
        }
    }
}

// ---- B: set one bit per edge; count first-setters inline (warp-aggregated) -
__global__ void k_edges(const unsigned int* __restrict__ w) {
    const int e = blockIdx.x * blockDim.x + threadIdx.x;   // EE threads exactly
    unsigned int r, c;
    if (g_is64) { r = w[2 * e]; c = w[2 * (EE + e)]; }
    else        { r = w[e];     c = w[EE + e]; }
    bool valid = (r < NN) && (c < NN);
    bool isnew = false;
    if (valid) {
        unsigned int word = (r << 8) | (c >> 5);           // (r*8192+c)/32
        unsigned int bit  = 1u << (c & 31);
        unsigned int old  = atomicOr(&g_bitmap[word], bit);
        isnew = (old & bit) == 0u;
    }
    unsigned int m = __ballot_sync(0xffffffffu, isnew);
    if ((threadIdx.x & 31) == 0 && m)
        atomicAdd(&g_nnz, (unsigned long long)__popc(m));
}

// ---- C: write output + re-zero bitmap for the next replay ------------------
//   blocks [0,2048)      : zero bitmap (uint4)
//   blocks [2048,2112)   : x_pooled rows (colsum recompute from L2 partials)
//   blocks [2112,2176)   : adj_pooled rows (scalar broadcast)
__global__ void k_C(float* __restrict__ out, int out_size) {
    const int b = blockIdx.x;
    const int t = threadIdx.x;
    if (b < 2048) {
        reinterpret_cast<uint4*>(g_bitmap)[b * 256 + t] = make_uint4(0u, 0u, 0u, 0u);
    } else if (b < 2048 + 64) {
        const int bb = b - 2048;
        float s = 0.0f;
        #pragma unroll
        for (int p = 0; p < NPART; ++p) s += g_partial[p][t];
        s *= (1.0f / 256.0f);
        #pragma unroll
        for (int r = 0; r < 4; ++r) {
            int i = (bb * 4 + r) * CC + t;                 // rows 4bb..4bb+3
            if (i < out_size) out[i] = s;
        }
    } else {
        const int bb = b - 2112;
        const float v = (float)g_nnz * (1.0f / 65536.0f);
        const int base = 65536 + bb * 1024;
        #pragma unroll
        for (int r = 0; r < 4; ++r) {
            int i = base + r * 256 + t;
            if (i < out_size) out[i] = v;
        }
    }
}

extern "C" void kernel_launch(void* const* d_in, const int* in_sizes, int n_in,
                              void* d_out, int out_size) {
    const float*        x  = (const float*)d_in[0];
    const unsigned int* ei = (const unsigned int*)d_in[1];
    float* out = (float*)d_out;

    k_A<<<NPART + 1, 256>>>(x, ei);
    k_edges<<<EE / 256, 256>>>(ei);
    k_C<<<2176, 256>>>(out, out_size);
}

// round 15
// speedup vs baseline: 1.5338x; 1.3797x over previous
#include <cuda_runtime.h>
#include <cuda_bf16.h>

// ENAHPool collapses analytically (verified R8/R12: rel_err ~4e-7):
//   S = softmax(assign,-1) = 1/256 everywhere (assign rows are constant).
//   => x_pooled[p,c]   = colsum(x)[c] / 256          (broadcast over p)
//   => adj_pooled[p,q] = nnz_unique(edges) / 65536   (scalar broadcast)
//
// R14 (rule-compliant; no call counters):
//  * k_A: 1024 blocks, float4 loads, smem block-reduce -> 1024 partials.
//  * k_edges: atomicOr dedup + BLOCK-aggregated nnz (1024 atomics total,
//    avoids single-address atomic serialization) + 8 reducer blocks.
//  * k_C: clears exactly the touched bitmap words by edge-list scatter
//    (L2-resident re-read, replaces 8MB memset) + 128 output blocks.
//    Bitmap is all-zero on entry to EVERY call -> deterministic.

#define NN 8192
#define EE 262144
#define CC 256
#define BM_WORDS 2097152          // 8192*8192 / 32 = 8 MB bitmap
#define NB 1024
#define TTOT (NB * 256)           // 262144 threads in k_A

__device__ unsigned int       g_bitmap[BM_WORDS];   // zero-init; self-cleaning
__device__ unsigned long long g_nnz;
__device__ int                g_is64;
__device__ float              g_partial [NB][CC];   // 1 MB
__device__ float              g_partial2[8][CC];

// ---- A: colsum partials (blocks 0..1023) + control block (1024) ------------
__global__ void k_A(const float4* __restrict__ x4, const unsigned int* __restrict__ w) {
    const int b = blockIdx.x;
    const int t = threadIdx.x;
    if (b < NB) {
        // 8192*256/4 = 524288 float4s, 262144 threads -> 2 strided each.
        const int j = b * 256 + t;
        float4 v0 = x4[j];
        float4 v1 = x4[j + TTOT];             // TTOT % 64 == 0 -> same col group
        float4 a = make_float4(v0.x + v1.x, v0.y + v1.y, v0.z + v1.z, v0.w + v1.w);
        __shared__ float4 sh[256];
        sh[t] = a;
        __syncthreads();
        if (t < 64) {                         // col group of thread t is t%64
            float4 s0 = sh[t], s1 = sh[t + 64], s2 = sh[t + 128], s3 = sh[t + 192];
            g_partial[b][t * 4 + 0] = (s0.x + s1.x) + (s2.x + s3.x);
            g_partial[b][t * 4 + 1] = (s0.y + s1.y) + (s2.y + s3.y);
            g_partial[b][t * 4 + 2] = (s0.z + s1.z) + (s2.z + s3.z);
            g_partial[b][t * 4 + 3] = (s0.w + s1.w) + (s2.w + s3.w);
        }
    } else {
        // int64 little-endian indices (vals < 8192) => odd 32-bit words all 0
        __shared__ unsigned int acc[256];
        acc[t] = w[2 * t + 1];
        __syncthreads();
        for (int s = 128; s; s >>= 1) {
            if (t < s) acc[t] |= acc[t + s];
            __syncthreads();
        }
        if (t == 0) {
            g_is64 = (acc[0] == 0u) ? 1 : 0;
            g_nnz  = 0ULL;
        }
    }
}

// ---- B: edge dedup + block-aggregated nnz; +8 partial-reducer blocks -------
__global__ void k_edges(const unsigned int* __restrict__ w) {
    const int b = blockIdx.x;
    const int t = threadIdx.x;
    if (b < NB) {
        const int e = b * 256 + t;            // exactly EE threads
        unsigned int r, c;
        if (g_is64) { r = w[2 * e]; c = w[2 * (EE + e)]; }
        else        { r = w[e];     c = w[EE + e]; }
        bool isnew = false;
        if (r < NN && c < NN) {
            unsigned int word = (r << 8) | (c >> 5);
            unsigned int bit  = 1u << (c & 31);
            isnew = (atomicOr(&g_bitmap[word], bit) & bit) == 0u;
        }
        unsigned int m = __ballot_sync(0xffffffffu, isnew);
        __shared__ unsigned int wc[8];
        if ((t & 31) == 0) wc[t >> 5] = __popc(m);
        __syncthreads();
        if (t == 0) {
            unsigned int tot = wc[0] + wc[1] + wc[2] + wc[3]
                             + wc[4] + wc[5] + wc[6] + wc[7];
            if (tot) atomicAdd(&g_nnz, (unsigned long long)tot);
        }
    } else {
        // reducer block b2 = b - NB in [0,8): sum partial rows [128*b2, +128)
        const int b2 = b - NB;
        float s0 = 0.f, s1 = 0.f, s2 = 0.f, s3 = 0.f;
        const int base = b2 * 128;
        #pragma unroll 4
        for (int p = 0; p < 128; p += 4) {
            s0 += g_partial[base + p + 0][t];
            s1 += g_partial[base + p + 1][t];
            s2 += g_partial[base + p + 2][t];
            s3 += g_partial[base + p + 3][t];
        }
        g_partial2[b2][t] = (s0 + s1) + (s2 + s3);
    }
}

// ---- C: scatter-clear touched bitmap words + write output ------------------
//   blocks [0,1024)      : store 0 to each edge's bitmap word (benign race)
//   blocks [1024,1088)   : x_pooled rows (fold 8 partials, broadcast)
//   blocks [1088,1152)   : adj_pooled rows (scalar broadcast)
__global__ void k_C(const unsigned int* __restrict__ w,
                    float* __restrict__ out, int out_size) {
    const int b = blockIdx.x;
    const int t = threadIdx.x;
    if (b < NB) {
        const int e = b * 256 + t;
        unsigned int r, c;
        if (g_is64) { r = w[2 * e]; c = w[2 * (EE + e)]; }
        else        { r = w[e];     c = w[EE + e]; }
        if (r < NN && c < NN)
            g_bitmap[(r << 8) | (c >> 5)] = 0u;   // racing identical stores
    } else if (b < NB + 64) {
        const int bb = b - NB;
        float s = 0.f;
        #pragma unroll
        for (int p = 0; p < 8; ++p) s += g_partial2[p][t];
        s *= (1.0f / 256.0f);
        #pragma unroll
        for (int r = 0; r < 4; ++r) {
            int i = (bb * 4 + r) * CC + t;
            if (i < out_size) out[i] = s;
        }
    } else {
        const int bb = b - NB - 64;
        const float v = (float)g_nnz * (1.0f / 65536.0f);
        const int base = 65536 + bb * 1024;
        #pragma unroll
        for (int r = 0; r < 4; ++r) {
            int i = base + r * 256 + t;
            if (i < out_size) out[i] = v;
        }
    }
}

extern "C" void kernel_launch(void* const* d_in, const int* in_sizes, int n_in,
                              void* d_out, int out_size) {
    const float4*       x4 = (const float4*)d_in[0];
    const unsigned int* ei = (const unsigned int*)d_in[1];
    float* out = (float*)d_out;

    k_A<<<NB + 1, 256>>>(x4, ei);
    k_edges<<<NB + 8, 256>>>(ei);
    k_C<<<NB + 128, 256>>>(ei, out, out_size);
}